// round 1
// baseline (speedup 1.0000x reference)
#include <cuda_runtime.h>

#define NN 3072
#define IN_DIM 512
#define OUT_DIM 64
#define HEADS 8
#define NEG_SLOPE 0.2f
#define EMAX 512   // max edges per row (mean ~31, p(>70) astronomically small)

// Scratch (no allocations allowed): h [H,N,64], f_src/f_dst [H,N]
__device__ float g_h[HEADS * NN * OUT_DIM];
__device__ float g_fs[HEADS * NN];
__device__ float g_fd[HEADS * NN];

// ---------------------------------------------------------------------------
// Kernel 1: per-head projection h[h,n,o] = sum_k x[n,k] * W[h,k,o]
// Grid: (N/64, HEADS), 256 threads. 64x64 output tile, 4x4 per-thread microtile.
// ---------------------------------------------------------------------------
__global__ __launch_bounds__(256) void gat_proj(const float* __restrict__ x,
                                                const float* __restrict__ W) {
    int head = blockIdx.y;
    int n0   = blockIdx.x * 64;
    int t    = threadIdx.x;
    int tx4  = (t & 15) * 4;   // output cols [tx4, tx4+3]
    int ty4  = (t >> 4) * 4;   // rows [ty4, ty4+3]

    __shared__ float xs[64][33];   // [row][k], padded
    __shared__ float ws[32][64];   // [k][col]

    float acc[4][4] = {};
    const float* Wh = W + (size_t)head * IN_DIM * OUT_DIM;

    for (int kk = 0; kk < IN_DIM; kk += 32) {
#pragma unroll
        for (int i = 0; i < 8; i++) {          // 64*32 = 2048 elems, 8/thread
            int li = t + i * 256;
            int r = li >> 5, c = li & 31;
            xs[r][c] = x[(size_t)(n0 + r) * IN_DIM + kk + c];
        }
#pragma unroll
        for (int i = 0; i < 8; i++) {          // 32*64 = 2048 elems
            int li = t + i * 256;
            int r = li >> 6, c = li & 63;
            ws[r][c] = Wh[(size_t)(kk + r) * OUT_DIM + c];
        }
        __syncthreads();
#pragma unroll
        for (int k = 0; k < 32; k++) {
            float a[4], b[4];
#pragma unroll
            for (int i = 0; i < 4; i++) a[i] = xs[ty4 + i][k];
#pragma unroll
            for (int j = 0; j < 4; j++) b[j] = ws[k][tx4 + j];
#pragma unroll
            for (int i = 0; i < 4; i++)
#pragma unroll
                for (int j = 0; j < 4; j++)
                    acc[i][j] += a[i] * b[j];
        }
        __syncthreads();
    }
#pragma unroll
    for (int i = 0; i < 4; i++)
#pragma unroll
        for (int j = 0; j < 4; j++)
            g_h[((size_t)head * NN + n0 + ty4 + i) * OUT_DIM + tx4 + j] = acc[i][j];
}

// ---------------------------------------------------------------------------
// Kernel 2: f_src[h,n] = h[h,n,:] . a_src[h,:]   (and same for f_dst)
// One warp per (h, n).
// ---------------------------------------------------------------------------
__global__ __launch_bounds__(256) void gat_fvec(const float* __restrict__ a_src,
                                                const float* __restrict__ a_dst) {
    int gw   = (blockIdx.x * blockDim.x + threadIdx.x) >> 5;
    int lane = threadIdx.x & 31;
    if (gw >= HEADS * NN) return;
    int head = gw / NN;

    const float* hr = g_h + (size_t)gw * OUT_DIM;
    float v0 = hr[lane], v1 = hr[lane + 32];
    float s = v0 * a_src[head * OUT_DIM + lane] + v1 * a_src[head * OUT_DIM + lane + 32];
    float d = v0 * a_dst[head * OUT_DIM + lane] + v1 * a_dst[head * OUT_DIM + lane + 32];
#pragma unroll
    for (int off = 16; off; off >>= 1) {
        s += __shfl_xor_sync(0xffffffffu, s, off);
        d += __shfl_xor_sync(0xffffffffu, d, off);
    }
    if (lane == 0) { g_fs[gw] = s; g_fd[gw] = d; }
}

// ---------------------------------------------------------------------------
// Kernel 3: fused masked softmax + aggregation.
// One block per destination row i. Threads compact nonzero adj indices into
// shared, then warp w handles head w: logits -> max -> exp/sum -> weighted
// sum of h[j] rows. Output written directly in concat layout [N, H*64].
// ---------------------------------------------------------------------------
__global__ __launch_bounds__(256) void gat_attn(const float* __restrict__ adj,
                                                float* __restrict__ out) {
    int i = blockIdx.x;
    int t = threadIdx.x;

    __shared__ int   s_idx[EMAX];
    __shared__ float s_w[HEADS][EMAX];
    __shared__ int   s_cnt;

    if (t == 0) s_cnt = 0;
    __syncthreads();

    const float* arow = adj + (size_t)i * NN;
    for (int j = t; j < NN; j += 256) {
        if (arow[j] > 0.0f) {
            int p = atomicAdd(&s_cnt, 1);
            if (p < EMAX) s_idx[p] = j;
        }
    }
    __syncthreads();
    int E = min(s_cnt, EMAX);   // always >= 1 (self-loop)

    int head = t >> 5;
    int lane = t & 31;
    float fs = g_fs[head * NN + i];

    // pass 1: logits + max
    float m = -1e30f;
    for (int k = lane; k < E; k += 32) {
        int j = s_idx[k];
        float e = fs + g_fd[head * NN + j];
        e = (e > 0.0f) ? e : NEG_SLOPE * e;
        s_w[head][k] = e;
        m = fmaxf(m, e);
    }
#pragma unroll
    for (int off = 16; off; off >>= 1)
        m = fmaxf(m, __shfl_xor_sync(0xffffffffu, m, off));

    // pass 2: exp + sum
    float s = 0.0f;
    for (int k = lane; k < E; k += 32) {
        float w = __expf(s_w[head][k] - m);
        s_w[head][k] = w;
        s += w;
    }
#pragma unroll
    for (int off = 16; off; off >>= 1)
        s += __shfl_xor_sync(0xffffffffu, s, off);
    float inv = 1.0f / s;
    __syncwarp();

    // pass 3: weighted aggregation; lane owns output dims (lane, lane+32)
    float acc0 = 0.0f, acc1 = 0.0f;
    const float* hb = g_h + (size_t)head * NN * OUT_DIM;
    for (int k = 0; k < E; k++) {
        int j = s_idx[k];
        float w = s_w[head][k];
        const float* hr = hb + (size_t)j * OUT_DIM;
        acc0 += w * hr[lane];
        acc1 += w * hr[lane + 32];
    }
    size_t o = (size_t)i * (HEADS * OUT_DIM) + head * OUT_DIM;
    out[o + lane]      = acc0 * inv;
    out[o + lane + 32] = acc1 * inv;
}

// ---------------------------------------------------------------------------
extern "C" void kernel_launch(void* const* d_in, const int* in_sizes, int n_in,
                              void* d_out, int out_size) {
    const float* x     = (const float*)d_in[0];
    const float* adj   = (const float*)d_in[1];
    const float* W     = (const float*)d_in[2];
    const float* a_src = (const float*)d_in[3];
    const float* a_dst = (const float*)d_in[4];
    float* out = (float*)d_out;

    dim3 g1(NN / 64, HEADS);
    gat_proj<<<g1, 256>>>(x, W);
    gat_fvec<<<(HEADS * NN * 32 + 255) / 256, 256>>>(a_src, a_dst);
    gat_attn<<<NN, 256>>>(adj, out);
}

// round 3
// speedup vs baseline: 1.1011x; 1.1011x over previous
#include <cuda_runtime.h>
#include <cuda_bf16.h>
#include <stdint.h>

#define NN 3072
#define IN_DIM 512
#define OUT_DIM 64
#define HEADS 8
#define COLS 512          // HEADS*OUT_DIM
#define NEG_SLOPE 0.2f
#define EMAX 512

// ---------------- scratch (no allocations allowed) ----------------
__device__ float g_h[(size_t)NN * COLS];               // h concat layout [N, 512]
__device__ float g_fs[HEADS * NN];
__device__ float g_fd[HEADS * NN];
__device__ __nv_bfloat16 g_Wh[(size_t)COLS * IN_DIM];  // W^T hi  [col][k]
__device__ __nv_bfloat16 g_Wl[(size_t)COLS * IN_DIM];  // W^T lo  [col][k]

__device__ __forceinline__ uint32_t smem_u32(const void* p) {
    uint32_t a;
    asm("{ .reg .u64 t; cvta.to.shared.u64 t, %1; cvt.u32.u64 %0, t; }" : "=r"(a) : "l"(p));
    return a;
}
__device__ __forceinline__ void ldmatrix_x4(uint32_t& r0, uint32_t& r1, uint32_t& r2,
                                            uint32_t& r3, uint32_t addr) {
    asm volatile("ldmatrix.sync.aligned.m8n8.x4.shared.b16 {%0,%1,%2,%3}, [%4];"
                 : "=r"(r0), "=r"(r1), "=r"(r2), "=r"(r3) : "r"(addr));
}
__device__ __forceinline__ void mma_bf16(float* d, const uint32_t* a, const uint32_t* b) {
    asm volatile(
        "mma.sync.aligned.m16n8k16.row.col.f32.bf16.bf16.f32 "
        "{%0,%1,%2,%3}, {%4,%5,%6,%7}, {%8,%9}, {%0,%1,%2,%3};"
        : "+f"(d[0]), "+f"(d[1]), "+f"(d[2]), "+f"(d[3])
        : "r"(a[0]), "r"(a[1]), "r"(a[2]), "r"(a[3]), "r"(b[0]), "r"(b[1]));
}

// ---------------------------------------------------------------------------
// Kernel 0: split/transpose W [H,IN,OUT] fp32 -> g_Wh/g_Wl [H*64+o][k] bf16
// ---------------------------------------------------------------------------
__global__ __launch_bounds__(256) void w_split(const float* __restrict__ W) {
    int h = blockIdx.x, kt = blockIdx.y;
    __shared__ float ts[64][65];
    int t = threadIdx.x;
    const float* Wb = W + ((size_t)h * IN_DIM + kt * 64) * OUT_DIM;
#pragma unroll
    for (int i = 0; i < 16; i++) {
        int idx = t + i * 256;
        int r = idx >> 6, c = idx & 63;
        ts[r][c] = Wb[r * OUT_DIM + c];
    }
    __syncthreads();
#pragma unroll
    for (int i = 0; i < 16; i++) {
        int idx = t + i * 256;
        int o = idx >> 6, k = idx & 63;
        float v = ts[k][o];
        __nv_bfloat16 hi = __float2bfloat16_rn(v);
        __nv_bfloat16 lo = __float2bfloat16_rn(v - __bfloat162float(hi));
        size_t off = (size_t)(h * 64 + o) * IN_DIM + kt * 64 + k;
        g_Wh[off] = hi;
        g_Wl[off] = lo;
    }
}

// ---------------------------------------------------------------------------
// Kernel 1: split-bf16 mma.sync GEMM  h = x @ W'  (3072x512 @ 512x512)
// CTA tile 128x128, 8 warps in 2(M)x4(N), warp tile 64x32, K-step 32.
// Smem stride 40 bf16 (80 B): 16B-aligned rows, conflict-free ldmatrix.
// ---------------------------------------------------------------------------
#define STRIDE 40

__global__ __launch_bounds__(256) void gat_gemm(const float* __restrict__ x) {
    __shared__ __align__(16) __nv_bfloat16 sAh[128 * STRIDE];
    __shared__ __align__(16) __nv_bfloat16 sAl[128 * STRIDE];
    __shared__ __align__(16) __nv_bfloat16 sBh[128 * STRIDE];
    __shared__ __align__(16) __nv_bfloat16 sBl[128 * STRIDE];

    int t = threadIdx.x;
    int wid = t >> 5, lane = t & 31;
    int n0 = blockIdx.x * 128;
    int c0 = blockIdx.y * 128;
    int wm = (wid & 1) * 64;   // warp row offset
    int wn = (wid >> 1) * 32;  // warp col offset

    float acc[4][4][4] = {};

    const uint32_t aAh = smem_u32(sAh), aAl = smem_u32(sAl);
    const uint32_t aBh = smem_u32(sBh), aBl = smem_u32(sBl);

    // ldmatrix per-lane address offsets (element units)
    int a_row = wm + (lane & 15);              // + i*16
    int a_col8 = (lane >> 4) * 8;              // + ks
    // B x4: lanes 0-7: (n j*8+l, ks), 8-15: (same n, ks+8),
    //       16-23: (n j*8+8+l ... next frag), 24-31: (.., ks+8)
    int b_row = wn + (lane & 7) + ((lane >> 4) * 8);   // n index (+ j*16 per pair)
    int b_col8 = ((lane >> 3) & 1) * 8;                // + ks

    for (int kk = 0; kk < IN_DIM; kk += 32) {
        // --- load & split A: 128 rows x 32 k fp32 ---
#pragma unroll
        for (int i = 0; i < 4; i++) {
            int fidx = t + i * 256;            // 1024 float4
            int row = fidx >> 3, g = fidx & 7; // 8 float4 per row
            float4 v = *(const float4*)(x + (size_t)(n0 + row) * IN_DIM + kk + g * 4);
            __nv_bfloat16 h0 = __float2bfloat16_rn(v.x);
            __nv_bfloat16 h1 = __float2bfloat16_rn(v.y);
            __nv_bfloat16 h2 = __float2bfloat16_rn(v.z);
            __nv_bfloat16 h3 = __float2bfloat16_rn(v.w);
            __nv_bfloat16 l0 = __float2bfloat16_rn(v.x - __bfloat162float(h0));
            __nv_bfloat16 l1 = __float2bfloat16_rn(v.y - __bfloat162float(h1));
            __nv_bfloat16 l2 = __float2bfloat16_rn(v.z - __bfloat162float(h2));
            __nv_bfloat16 l3 = __float2bfloat16_rn(v.w - __bfloat162float(h3));
            uint2 ph, pl;
            ph.x = (uint32_t)__bfloat16_as_ushort(h0) | ((uint32_t)__bfloat16_as_ushort(h1) << 16);
            ph.y = (uint32_t)__bfloat16_as_ushort(h2) | ((uint32_t)__bfloat16_as_ushort(h3) << 16);
            pl.x = (uint32_t)__bfloat16_as_ushort(l0) | ((uint32_t)__bfloat16_as_ushort(l1) << 16);
            pl.y = (uint32_t)__bfloat16_as_ushort(l2) | ((uint32_t)__bfloat16_as_ushort(l3) << 16);
            int off = row * STRIDE + g * 4;
            *(uint2*)(sAh + off) = ph;
            *(uint2*)(sAl + off) = pl;
        }
        // --- copy B: 128 cols x 32 k bf16 hi/lo ---
#pragma unroll
        for (int i = 0; i < 2; i++) {
            int fidx = t + i * 256;            // 512 uint4
            int row = fidx >> 2, g = fidx & 3; // 4 uint4 (32 bf16) per row
            size_t gsrc = (size_t)(c0 + row) * IN_DIM + kk + g * 8;
            int off = row * STRIDE + g * 8;
            *(uint4*)(sBh + off) = *(const uint4*)(g_Wh + gsrc);
            *(uint4*)(sBl + off) = *(const uint4*)(g_Wl + gsrc);
        }
        __syncthreads();

#pragma unroll
        for (int ks = 0; ks < 32; ks += 16) {
            uint32_t ah[4][4], al[4][4], bh[4][2], bl[4][2];
#pragma unroll
            for (int i = 0; i < 4; i++) {
                uint32_t addr = 2u * ((a_row + i * 16) * STRIDE + ks + a_col8);
                ldmatrix_x4(ah[i][0], ah[i][1], ah[i][2], ah[i][3], aAh + addr);
                ldmatrix_x4(al[i][0], al[i][1], al[i][2], al[i][3], aAl + addr);
            }
#pragma unroll
            for (int jp = 0; jp < 2; jp++) {   // pairs of n8 frags
                uint32_t addr = 2u * ((b_row + jp * 16) * STRIDE + ks + b_col8);
                ldmatrix_x4(bh[2 * jp][0], bh[2 * jp][1], bh[2 * jp + 1][0], bh[2 * jp + 1][1],
                            aBh + addr);
                ldmatrix_x4(bl[2 * jp][0], bl[2 * jp][1], bl[2 * jp + 1][0], bl[2 * jp + 1][1],
                            aBl + addr);
            }
#pragma unroll
            for (int i = 0; i < 4; i++)
#pragma unroll
                for (int j = 0; j < 4; j++) {
                    mma_bf16(acc[i][j], ah[i], bh[j]);
                    mma_bf16(acc[i][j], al[i], bh[j]);
                    mma_bf16(acc[i][j], ah[i], bl[j]);
                }
        }
        __syncthreads();
    }

    // epilogue: acc[i][j] -> rows wm+i*16+{lane/4, +8}, cols wn+j*8+2*(lane%4)
#pragma unroll
    for (int i = 0; i < 4; i++) {
        int r0 = n0 + wm + i * 16 + (lane >> 2);
#pragma unroll
        for (int j = 0; j < 4; j++) {
            int c = c0 + wn + j * 8 + (lane & 3) * 2;
            *(float2*)(g_h + (size_t)r0 * COLS + c) = make_float2(acc[i][j][0], acc[i][j][1]);
            *(float2*)(g_h + (size_t)(r0 + 8) * COLS + c) = make_float2(acc[i][j][2], acc[i][j][3]);
        }
    }
}

// ---------------------------------------------------------------------------
// Kernel 2: f_src/f_dst. One warp per (head, n).
// ---------------------------------------------------------------------------
__global__ __launch_bounds__(256) void gat_fvec(const float* __restrict__ a_src,
                                                const float* __restrict__ a_dst) {
    int gw = (blockIdx.x * blockDim.x + threadIdx.x) >> 5;
    int lane = threadIdx.x & 31;
    if (gw >= HEADS * NN) return;
    int head = gw / NN, n = gw - head * NN;

    const float* hr = g_h + (size_t)n * COLS + head * OUT_DIM;
    float v0 = hr[lane], v1 = hr[lane + 32];
    float s = v0 * a_src[head * OUT_DIM + lane] + v1 * a_src[head * OUT_DIM + lane + 32];
    float d = v0 * a_dst[head * OUT_DIM + lane] + v1 * a_dst[head * OUT_DIM + lane + 32];
#pragma unroll
    for (int off = 16; off; off >>= 1) {
        s += __shfl_xor_sync(0xffffffffu, s, off);
        d += __shfl_xor_sync(0xffffffffu, d, off);
    }
    if (lane == 0) { g_fs[gw] = s; g_fd[gw] = d; }
}

// ---------------------------------------------------------------------------
// Kernel 3: fused masked softmax + aggregation (deterministic compaction).
// ---------------------------------------------------------------------------
__global__ __launch_bounds__(256) void gat_attn(const float* __restrict__ adj,
                                                float* __restrict__ out) {
    int i = blockIdx.x;
    int t = threadIdx.x;
    int lane = t & 31, wid = t >> 5;

    __shared__ int s_idx[EMAX];
    __shared__ float s_w[HEADS][EMAX];
    __shared__ int s_wsum[8];
    __shared__ int s_total;

    const float4* arow4 = (const float4*)(adj + (size_t)i * NN);
    int lidx[12];
    int cnt = 0;
#pragma unroll
    for (int it = 0; it < 3; it++) {
        int q = t + it * 256;
        float4 v = arow4[q];
        int j = q * 4;
        if (v.x > 0.f) lidx[cnt++] = j;
        if (v.y > 0.f) lidx[cnt++] = j + 1;
        if (v.z > 0.f) lidx[cnt++] = j + 2;
        if (v.w > 0.f) lidx[cnt++] = j + 3;
    }
    int incl = cnt;
#pragma unroll
    for (int off = 1; off < 32; off <<= 1) {
        int nv = __shfl_up_sync(0xffffffffu, incl, off);
        if (lane >= off) incl += nv;
    }
    if (lane == 31) s_wsum[wid] = incl;
    __syncthreads();
    if (t == 0) {
        int s = 0;
#pragma unroll
        for (int w = 0; w < 8; w++) { int v = s_wsum[w]; s_wsum[w] = s; s += v; }
        s_total = s;
    }
    __syncthreads();
    int base = s_wsum[wid] + incl - cnt;
    for (int k = 0; k < cnt; k++)
        if (base + k < EMAX) s_idx[base + k] = lidx[k];
    __syncthreads();
    int E = min(s_total, EMAX);

    int head = wid;
    float fs = g_fs[head * NN + i];

    float m = -1e30f;
    for (int k = lane; k < E; k += 32) {
        int j = s_idx[k];
        float e = fs + g_fd[head * NN + j];
        e = (e > 0.f) ? e : NEG_SLOPE * e;
        s_w[head][k] = e;
        m = fmaxf(m, e);
    }
#pragma unroll
    for (int off = 16; off; off >>= 1)
        m = fmaxf(m, __shfl_xor_sync(0xffffffffu, m, off));

    float s = 0.f;
    for (int k = lane; k < E; k += 32) {
        float w = __expf(s_w[head][k] - m);
        s_w[head][k] = w;
        s += w;
    }
#pragma unroll
    for (int off = 16; off; off >>= 1)
        s += __shfl_xor_sync(0xffffffffu, s, off);
    float inv = 1.f / s;
    __syncwarp();

    float acc0 = 0.f, acc1 = 0.f;
#pragma unroll 4
    for (int k = 0; k < E; k++) {
        int j = s_idx[k];
        float w = s_w[head][k];
        const float* hr = g_h + (size_t)j * COLS + head * OUT_DIM;
        acc0 += w * hr[lane];
        acc1 += w * hr[lane + 32];
    }
    size_t o = (size_t)i * COLS + head * OUT_DIM;
    out[o + lane] = acc0 * inv;
    out[o + lane + 32] = acc1 * inv;
}

// ---------------------------------------------------------------------------
extern "C" void kernel_launch(void* const* d_in, const int* in_sizes, int n_in,
                              void* d_out, int out_size) {
    const float* x     = (const float*)d_in[0];
    const float* adj   = (const float*)d_in[1];
    const float* W     = (const float*)d_in[2];
    const float* a_src = (const float*)d_in[3];
    const float* a_dst = (const float*)d_in[4];
    float* out = (float*)d_out;

    w_split<<<dim3(HEADS, IN_DIM / 64), 256>>>(W);
    gat_gemm<<<dim3(NN / 128, COLS / 128), 256>>>(x);
    gat_fvec<<<(HEADS * NN) / 8, 256>>>(a_src, a_dst);
    gat_attn<<<NN, 256>>>(adj, out);
}

// round 4
// speedup vs baseline: 1.5480x; 1.4059x over previous
#include <cuda_runtime.h>
#include <cuda_bf16.h>
#include <stdint.h>

#define NN 3072
#define IN_DIM 512
#define OUT_DIM 64
#define HEADS 8
#define COLS 512
#define NEG_SLOPE 0.2f
#define EMAX 512

// ---------------- scratch ----------------
__device__ float g_h[(size_t)NN * COLS];                 // [N][512]
__device__ float g_fs8[NN * HEADS];                      // [n][head]
__device__ float g_fd8[NN * HEADS];                      // [n][head]
__device__ __nv_bfloat16 g_Wh[(size_t)COLS * IN_DIM];    // W^T hi [col][k]
__device__ __nv_bfloat16 g_Wl[(size_t)COLS * IN_DIM];    // W^T lo [col][k]
__device__ __nv_bfloat16 g_Xh[(size_t)NN * IN_DIM];      // x hi [n][k]
__device__ __nv_bfloat16 g_Xl[(size_t)NN * IN_DIM];      // x lo [n][k]

__device__ __forceinline__ uint32_t smem_u32(const void* p) {
    uint32_t a;
    asm("{ .reg .u64 t; cvta.to.shared.u64 t, %1; cvt.u32.u64 %0, t; }" : "=r"(a) : "l"(p));
    return a;
}
__device__ __forceinline__ void ldmatrix_x4(uint32_t& r0, uint32_t& r1, uint32_t& r2,
                                            uint32_t& r3, uint32_t addr) {
    asm volatile("ldmatrix.sync.aligned.m8n8.x4.shared.b16 {%0,%1,%2,%3}, [%4];"
                 : "=r"(r0), "=r"(r1), "=r"(r2), "=r"(r3) : "r"(addr));
}
__device__ __forceinline__ void mma_bf16(float* d, const uint32_t* a, const uint32_t* b) {
    asm volatile(
        "mma.sync.aligned.m16n8k16.row.col.f32.bf16.bf16.f32 "
        "{%0,%1,%2,%3}, {%4,%5,%6,%7}, {%8,%9}, {%0,%1,%2,%3};"
        : "+f"(d[0]), "+f"(d[1]), "+f"(d[2]), "+f"(d[3])
        : "r"(a[0]), "r"(a[1]), "r"(a[2]), "r"(a[3]), "r"(b[0]), "r"(b[1]));
}
__device__ __forceinline__ void cp16(uint32_t dst, const void* src) {
    asm volatile("cp.async.ca.shared.global [%0], [%1], 16;" :: "r"(dst), "l"(src));
}
#define CP_COMMIT() asm volatile("cp.async.commit_group;" ::: "memory")
#define CP_WAIT(n)  asm volatile("cp.async.wait_group %0;" :: "n"(n) : "memory")

__device__ __forceinline__ uint2 split2(float a, float b) {
    __nv_bfloat16 h0 = __float2bfloat16_rn(a), h1 = __float2bfloat16_rn(b);
    uint2 r;
    r.x = (uint32_t)__bfloat16_as_ushort(h0) | ((uint32_t)__bfloat16_as_ushort(h1) << 16);
    __nv_bfloat16 l0 = __float2bfloat16_rn(a - __bfloat162float(h0));
    __nv_bfloat16 l1 = __float2bfloat16_rn(b - __bfloat162float(h1));
    r.y = (uint32_t)__bfloat16_as_ushort(l0) | ((uint32_t)__bfloat16_as_ushort(l1) << 16);
    return r;
}

// ---------------------------------------------------------------------------
// Kernel A: split x -> bf16 hi/lo
// ---------------------------------------------------------------------------
__global__ __launch_bounds__(256) void x_split(const float* __restrict__ x) {
    int gid = blockIdx.x * 256 + threadIdx.x;      // one float4 each
    float4 v = ((const float4*)x)[gid];
    uint2 p01 = split2(v.x, v.y);
    uint2 p23 = split2(v.z, v.w);
    ((uint2*)g_Xh)[gid] = make_uint2(p01.x, p23.x);
    ((uint2*)g_Xl)[gid] = make_uint2(p01.y, p23.y);
}

// ---------------------------------------------------------------------------
// Kernel B: split/transpose W [H,IN,OUT] -> g_Wh/g_Wl [H*64+o][k]
// ---------------------------------------------------------------------------
__global__ __launch_bounds__(256) void w_split(const float* __restrict__ W) {
    int h = blockIdx.x, kt = blockIdx.y;
    __shared__ float ts[64][65];
    int t = threadIdx.x;
    const float* Wb = W + ((size_t)h * IN_DIM + kt * 64) * OUT_DIM;
#pragma unroll
    for (int i = 0; i < 16; i++) {
        int idx = t + i * 256;
        ts[idx >> 6][idx & 63] = Wb[(idx >> 6) * OUT_DIM + (idx & 63)];
    }
    __syncthreads();
#pragma unroll
    for (int i = 0; i < 16; i++) {
        int idx = t + i * 256;
        int o = idx >> 6, k = idx & 63;
        float v = ts[k][o];
        __nv_bfloat16 hi = __float2bfloat16_rn(v);
        __nv_bfloat16 lo = __float2bfloat16_rn(v - __bfloat162float(hi));
        size_t off = (size_t)(h * 64 + o) * IN_DIM + kt * 64 + k;
        g_Wh[off] = hi;
        g_Wl[off] = lo;
    }
}

// ---------------------------------------------------------------------------
// Kernel C: split-bf16 mma.sync GEMM, 64x64 tiles, cp.async double-buffered.
// Grid (48,8) = 384 CTAs. 8 warps 2(M)x4(N), warp tile 32x16, K-step 32.
// ---------------------------------------------------------------------------
#define STRIDE 40

__global__ __launch_bounds__(256) void gat_gemm() {
    __shared__ __align__(16) __nv_bfloat16 sA[2][2][64 * STRIDE];
    __shared__ __align__(16) __nv_bfloat16 sB[2][2][64 * STRIDE];

    int t = threadIdx.x;
    int wid = t >> 5, lane = t & 31;
    int n0 = blockIdx.x * 64;
    int c0 = blockIdx.y * 64;
    int wm = (wid & 1) * 32;
    int wn = (wid >> 1) * 16;

    float acc[2][2][4] = {};

    int lrow = t >> 2, lg = (t & 3) * 8;            // loader: row 0..63, 16B chunk
    size_t asrc = (size_t)(n0 + lrow) * IN_DIM + lg;
    size_t bsrc = (size_t)(c0 + lrow) * IN_DIM + lg;
    uint32_t sdst = 2u * (lrow * STRIDE + lg);

    uint32_t aA0 = smem_u32(sA[0][0]), aA1 = smem_u32(sA[1][0]);
    uint32_t bytesA = 2u * 64 * STRIDE;

    // prefetch stage 0
    {
        uint32_t d0 = aA0 + sdst;
        cp16(d0, g_Xh + asrc);
        cp16(d0 + bytesA, g_Xl + asrc);
        uint32_t d1 = smem_u32(sB[0][0]) + sdst;
        cp16(d1, g_Wh + bsrc);
        cp16(d1 + bytesA, g_Wl + bsrc);
        CP_COMMIT();
    }

    int a_off = 2u * ((wm + (lane & 15)) * STRIDE + (lane >> 4) * 8);
    int b_off = 2u * ((wn + (lane & 7) + ((lane >> 4) * 8)) * STRIDE + ((lane >> 3) & 1) * 8);

    for (int it = 0; it < 16; it++) {
        int cur = it & 1;
        if (it < 15) {
            int nxt = cur ^ 1;
            int kk = (it + 1) * 32;
            uint32_t dA = (nxt ? aA1 : aA0) + sdst;
            cp16(dA, g_Xh + asrc + kk);
            cp16(dA + bytesA, g_Xl + asrc + kk);
            uint32_t dB = smem_u32(sB[nxt][0]) + sdst;
            cp16(dB, g_Wh + bsrc + kk);
            cp16(dB + bytesA, g_Wl + bsrc + kk);
            CP_COMMIT();
            CP_WAIT(1);
        } else {
            CP_WAIT(0);
        }
        __syncthreads();

        uint32_t aAh = smem_u32(sA[cur][0]), aAl = smem_u32(sA[cur][1]);
        uint32_t aBh = smem_u32(sB[cur][0]), aBl = smem_u32(sB[cur][1]);
#pragma unroll
        for (int ks = 0; ks < 32; ks += 16) {
            uint32_t ah[2][4], al[2][4], bh[2][2], bl[2][2];
#pragma unroll
            for (int i = 0; i < 2; i++) {
                uint32_t ad = a_off + 2u * (i * 16 * STRIDE + ks);
                ldmatrix_x4(ah[i][0], ah[i][1], ah[i][2], ah[i][3], aAh + ad);
                ldmatrix_x4(al[i][0], al[i][1], al[i][2], al[i][3], aAl + ad);
            }
            {
                uint32_t bd = b_off + 2u * ks;
                ldmatrix_x4(bh[0][0], bh[0][1], bh[1][0], bh[1][1], aBh + bd);
                ldmatrix_x4(bl[0][0], bl[0][1], bl[1][0], bl[1][1], aBl + bd);
            }
#pragma unroll
            for (int i = 0; i < 2; i++)
#pragma unroll
                for (int j = 0; j < 2; j++) {
                    mma_bf16(acc[i][j], ah[i], bh[j]);
                    mma_bf16(acc[i][j], al[i], bh[j]);
                    mma_bf16(acc[i][j], ah[i], bl[j]);
                }
        }
        __syncthreads();
    }

#pragma unroll
    for (int i = 0; i < 2; i++) {
        int r0 = n0 + wm + i * 16 + (lane >> 2);
#pragma unroll
        for (int j = 0; j < 2; j++) {
            int c = c0 + wn + j * 8 + (lane & 3) * 2;
            *(float2*)(g_h + (size_t)r0 * COLS + c) = make_float2(acc[i][j][0], acc[i][j][1]);
            *(float2*)(g_h + (size_t)(r0 + 8) * COLS + c) = make_float2(acc[i][j][2], acc[i][j][3]);
        }
    }
}

// ---------------------------------------------------------------------------
// Kernel D: f_src/f_dst into [n][head] layout. One warp per (head, n).
// ---------------------------------------------------------------------------
__global__ __launch_bounds__(256) void gat_fvec(const float* __restrict__ a_src,
                                                const float* __restrict__ a_dst) {
    int gw = (blockIdx.x * blockDim.x + threadIdx.x) >> 5;
    int lane = threadIdx.x & 31;
    int head = gw / NN, n = gw - head * NN;

    const float* hr = g_h + (size_t)n * COLS + head * OUT_DIM;
    float v0 = hr[lane], v1 = hr[lane + 32];
    float s = v0 * a_src[head * OUT_DIM + lane] + v1 * a_src[head * OUT_DIM + lane + 32];
    float d = v0 * a_dst[head * OUT_DIM + lane] + v1 * a_dst[head * OUT_DIM + lane + 32];
#pragma unroll
    for (int off = 16; off; off >>= 1) {
        s += __shfl_xor_sync(0xffffffffu, s, off);
        d += __shfl_xor_sync(0xffffffffu, d, off);
    }
    if (lane == 0) { g_fs8[n * HEADS + head] = s; g_fd8[n * HEADS + head] = d; }
}

// ---------------------------------------------------------------------------
// Kernel E: fused masked softmax + all-heads aggregation.
// Block per row. Logits: thread (k-group, head). Aggregation: warp per
// edge-stride streams full 2KB h row for all heads; 8-way shared reduction.
// ---------------------------------------------------------------------------
__global__ __launch_bounds__(256) void gat_attn(const float* __restrict__ adj,
                                                float* __restrict__ out) {
    int i = blockIdx.x;
    int t = threadIdx.x;
    int lane = t & 31, wid = t >> 5;
    int head8 = t & 7;

    __shared__ int   s_idx[EMAX];
    __shared__ float s_w[EMAX][8];      // 16KB
    __shared__ float s_agg[8][512];     // 16KB
    __shared__ float s_red[8][8];
    __shared__ float s_m[8], s_inv[8], s_fs[8];
    __shared__ int   s_wsum[8];
    __shared__ int   s_total;

    // ---- Phase A: scan adjacency row, deterministic compaction ----
    const float4* arow4 = (const float4*)(adj + (size_t)i * NN);
    int lidx[12];
    int cnt = 0;
#pragma unroll
    for (int it = 0; it < 3; it++) {
        int q = t + it * 256;
        float4 v = arow4[q];
        int j = q * 4;
        if (v.x > 0.f) lidx[cnt++] = j;
        if (v.y > 0.f) lidx[cnt++] = j + 1;
        if (v.z > 0.f) lidx[cnt++] = j + 2;
        if (v.w > 0.f) lidx[cnt++] = j + 3;
    }
    int incl = cnt;
#pragma unroll
    for (int off = 1; off < 32; off <<= 1) {
        int nv = __shfl_up_sync(0xffffffffu, incl, off);
        if (lane >= off) incl += nv;
    }
    if (lane == 31) s_wsum[wid] = incl;
    if (t < 8) s_fs[t] = g_fs8[i * HEADS + t];
    __syncthreads();
    if (t == 0) {
        int s = 0;
#pragma unroll
        for (int w = 0; w < 8; w++) { int v = s_wsum[w]; s_wsum[w] = s; s += v; }
        s_total = s;
    }
    __syncthreads();
    int base = s_wsum[wid] + incl - cnt;
    for (int k = 0; k < cnt; k++)
        if (base + k < EMAX) s_idx[base + k] = lidx[k];
    __syncthreads();
    int E = min(s_total, EMAX);

    // ---- Phase B: logits + per-head max ----
    float fsv = s_fs[head8];
    float m = -1e30f;
    for (int k = (t >> 3); k < E; k += 32) {
        float e = fsv + g_fd8[s_idx[k] * HEADS + head8];
        e = (e > 0.f) ? e : NEG_SLOPE * e;
        s_w[k][head8] = e;
        m = fmaxf(m, e);
    }
    m = fmaxf(m, __shfl_xor_sync(0xffffffffu, m, 8));
    m = fmaxf(m, __shfl_xor_sync(0xffffffffu, m, 16));
    if (lane < 8) s_red[wid][lane] = m;
    __syncthreads();
    if (t < 8) {
        float mm = s_red[0][t];
#pragma unroll
        for (int w = 1; w < 8; w++) mm = fmaxf(mm, s_red[w][t]);
        s_m[t] = mm;
    }
    __syncthreads();

    // exp + per-head sum
    float mh = s_m[head8];
    float sum = 0.f;
    for (int k = (t >> 3); k < E; k += 32) {
        float w = __expf(s_w[k][head8] - mh);
        s_w[k][head8] = w;
        sum += w;
    }
    sum += __shfl_xor_sync(0xffffffffu, sum, 8);
    sum += __shfl_xor_sync(0xffffffffu, sum, 16);
    if (lane < 8) s_red[wid][lane] = sum;
    __syncthreads();
    if (t < 8) {
        float ss = s_red[0][t];
#pragma unroll
        for (int w = 1; w < 8; w++) ss += s_red[w][t];
        s_inv[t] = 1.f / ss;
    }
    __syncthreads();

    // ---- Phase C: aggregation, warp w handles edges k ≡ w (mod 8) ----
    float acc[16] = {};
    for (int k = wid; k < E; k += 8) {
        int j = s_idx[k];
        float4 wa = *(const float4*)&s_w[k][0];
        float4 wb = *(const float4*)&s_w[k][4];
        float w8[8] = {wa.x, wa.y, wa.z, wa.w, wb.x, wb.y, wb.z, wb.w};
        const float* hr = g_h + (size_t)j * COLS + lane;
#pragma unroll
        for (int f = 0; f < 16; f++)
            acc[f] += w8[f >> 1] * hr[f * 32];
    }
#pragma unroll
    for (int f = 0; f < 16; f++)
        s_agg[wid][f * 32 + lane] = acc[f];
    __syncthreads();

    // final cross-warp reduce + normalize; thread owns cols t and t+256
#pragma unroll
    for (int half = 0; half < 2; half++) {
        int c = t + half * 256;
        float s = s_agg[0][c];
#pragma unroll
        for (int w = 1; w < 8; w++) s += s_agg[w][c];
        out[(size_t)i * COLS + c] = s * s_inv[c >> 6];
    }
}

// ---------------------------------------------------------------------------
extern "C" void kernel_launch(void* const* d_in, const int* in_sizes, int n_in,
                              void* d_out, int out_size) {
    const float* x     = (const float*)d_in[0];
    const float* adj   = (const float*)d_in[1];
    const float* W     = (const float*)d_in[2];
    const float* a_src = (const float*)d_in[3];
    const float* a_dst = (const float*)d_in[4];
    float* out = (float*)d_out;

    x_split<<<NN * IN_DIM / 1024, 256>>>(x);
    w_split<<<dim3(HEADS, IN_DIM / 64), 256>>>(W);
    gat_gemm<<<dim3(NN / 64, COLS / 64), 256>>>();
    gat_fvec<<<HEADS * NN / 8, 256>>>(a_src, a_dst);
    gat_attn<<<NN, 256>>>(adj, out);
}

// round 7
// speedup vs baseline: 1.6866x; 1.0895x over previous
#include <cuda_runtime.h>
#include <cuda_bf16.h>
#include <stdint.h>

#define NN 3072
#define IN_DIM 512
#define OUT_DIM 64
#define HEADS 8
#define COLS 512
#define NEG_SLOPE 0.2f
#define EMAX 512

// ---------------- scratch ----------------
__device__ float g_h[(size_t)NN * COLS];                 // [N][512]
__device__ float g_fs8[NN * HEADS];                      // [n][head]
__device__ float g_fd8[NN * HEADS];                      // [n][head]
__device__ __nv_bfloat16 g_Wh[(size_t)COLS * IN_DIM];    // W^T hi [col][k]
__device__ __nv_bfloat16 g_Wl[(size_t)COLS * IN_DIM];    // W^T lo [col][k]
__device__ __nv_bfloat16 g_Xh[(size_t)NN * IN_DIM];      // x hi [n][k]
__device__ __nv_bfloat16 g_Xl[(size_t)NN * IN_DIM];      // x lo [n][k]

__device__ __forceinline__ uint32_t smem_u32(const void* p) {
    uint32_t a;
    asm("{ .reg .u64 t; cvta.to.shared.u64 t, %1; cvt.u32.u64 %0, t; }" : "=r"(a) : "l"(p));
    return a;
}
__device__ __forceinline__ void ldmatrix_x4(uint32_t& r0, uint32_t& r1, uint32_t& r2,
                                            uint32_t& r3, uint32_t addr) {
    asm volatile("ldmatrix.sync.aligned.m8n8.x4.shared.b16 {%0,%1,%2,%3}, [%4];"
                 : "=r"(r0), "=r"(r1), "=r"(r2), "=r"(r3) : "r"(addr));
}
__device__ __forceinline__ void mma_bf16(float* d, const uint32_t* a, const uint32_t* b) {
    asm volatile(
        "mma.sync.aligned.m16n8k16.row.col.f32.bf16.bf16.f32 "
        "{%0,%1,%2,%3}, {%4,%5,%6,%7}, {%8,%9}, {%0,%1,%2,%3};"
        : "+f"(d[0]), "+f"(d[1]), "+f"(d[2]), "+f"(d[3])
        : "r"(a[0]), "r"(a[1]), "r"(a[2]), "r"(a[3]), "r"(b[0]), "r"(b[1]));
}
__device__ __forceinline__ void cp16(uint32_t dst, const void* src) {
    asm volatile("cp.async.ca.shared.global [%0], [%1], 16;" :: "r"(dst), "l"(src));
}
#define CP_COMMIT() asm volatile("cp.async.commit_group;" ::: "memory")
#define CP_WAIT(n)  asm volatile("cp.async.wait_group %0;" :: "n"(n) : "memory")

__device__ __forceinline__ uint2 split2(float a, float b) {
    __nv_bfloat16 h0 = __float2bfloat16_rn(a), h1 = __float2bfloat16_rn(b);
    uint2 r;
    r.x = (uint32_t)__bfloat16_as_ushort(h0) | ((uint32_t)__bfloat16_as_ushort(h1) << 16);
    __nv_bfloat16 l0 = __float2bfloat16_rn(a - __bfloat162float(h0));
    __nv_bfloat16 l1 = __float2bfloat16_rn(b - __bfloat162float(h1));
    r.y = (uint32_t)__bfloat16_as_ushort(l0) | ((uint32_t)__bfloat16_as_ushort(l1) << 16);
    return r;
}

// ---------------------------------------------------------------------------
// Kernel A: split x -> bf16 hi/lo
// ---------------------------------------------------------------------------
__global__ __launch_bounds__(256) void x_split(const float* __restrict__ x) {
    int gid = blockIdx.x * 256 + threadIdx.x;
    float4 v = ((const float4*)x)[gid];
    uint2 p01 = split2(v.x, v.y);
    uint2 p23 = split2(v.z, v.w);
    ((uint2*)g_Xh)[gid] = make_uint2(p01.x, p23.x);
    ((uint2*)g_Xl)[gid] = make_uint2(p01.y, p23.y);
}

// ---------------------------------------------------------------------------
// Kernel B: split/transpose W [H,IN,OUT] -> g_Wh/g_Wl [H*64+o][k]
// ---------------------------------------------------------------------------
__global__ __launch_bounds__(256) void w_split(const float* __restrict__ W) {
    int h = blockIdx.x, kt = blockIdx.y;
    __shared__ float ts[64][65];
    int t = threadIdx.x;
    const float* Wb = W + ((size_t)h * IN_DIM + kt * 64) * OUT_DIM;
#pragma unroll
    for (int i = 0; i < 16; i++) {
        int idx = t + i * 256;
        ts[idx >> 6][idx & 63] = Wb[(idx >> 6) * OUT_DIM + (idx & 63)];
    }
    __syncthreads();
#pragma unroll
    for (int i = 0; i < 16; i++) {
        int idx = t + i * 256;
        int o = idx >> 6, k = idx & 63;
        float v = ts[k][o];
        __nv_bfloat16 hi = __float2bfloat16_rn(v);
        __nv_bfloat16 lo = __float2bfloat16_rn(v - __bfloat162float(hi));
        size_t off = (size_t)(h * 64 + o) * IN_DIM + kt * 64 + k;
        g_Wh[off] = hi;
        g_Wl[off] = lo;
    }
}

// ---------------------------------------------------------------------------
// Kernel C: split-bf16 mma.sync GEMM, 64x64 tiles, cp.async double-buffered,
// fused f_src/f_dst epilogue (each CTA's 64 cols = one complete head).
// ---------------------------------------------------------------------------
#define STRIDE 40

__global__ __launch_bounds__(256) void gat_gemm(const float* __restrict__ a_src,
                                                const float* __restrict__ a_dst) {
    __shared__ __align__(16) __nv_bfloat16 sA[2][2][64 * STRIDE];
    __shared__ __align__(16) __nv_bfloat16 sB[2][2][64 * STRIDE];
    __shared__ float s_fs[4][64];
    __shared__ float s_fd[4][64];

    int t = threadIdx.x;
    int wid = t >> 5, lane = t & 31;
    int n0 = blockIdx.x * 64;
    int c0 = blockIdx.y * 64;
    int wm = (wid & 1) * 32;
    int wn = (wid >> 1) * 16;
    int head = c0 >> 6;

    float acc[2][2][4] = {};

    int lrow = t >> 2, lg = (t & 3) * 8;
    size_t asrc = (size_t)(n0 + lrow) * IN_DIM + lg;
    size_t bsrc = (size_t)(c0 + lrow) * IN_DIM + lg;
    uint32_t sdst = 2u * (lrow * STRIDE + lg);

    uint32_t aA0 = smem_u32(sA[0][0]), aA1 = smem_u32(sA[1][0]);
    uint32_t bytesA = 2u * 64 * STRIDE;

    {
        uint32_t d0 = aA0 + sdst;
        cp16(d0, g_Xh + asrc);
        cp16(d0 + bytesA, g_Xl + asrc);
        uint32_t d1 = smem_u32(sB[0][0]) + sdst;
        cp16(d1, g_Wh + bsrc);
        cp16(d1 + bytesA, g_Wl + bsrc);
        CP_COMMIT();
    }

    int a_off = 2u * ((wm + (lane & 15)) * STRIDE + (lane >> 4) * 8);
    int b_off = 2u * ((wn + (lane & 7) + ((lane >> 4) * 8)) * STRIDE + ((lane >> 3) & 1) * 8);

    for (int it = 0; it < 16; it++) {
        int cur = it & 1;
        if (it < 15) {
            int nxt = cur ^ 1;
            int kk = (it + 1) * 32;
            uint32_t dA = (nxt ? aA1 : aA0) + sdst;
            cp16(dA, g_Xh + asrc + kk);
            cp16(dA + bytesA, g_Xl + asrc + kk);
            uint32_t dB = smem_u32(sB[nxt][0]) + sdst;
            cp16(dB, g_Wh + bsrc + kk);
            cp16(dB + bytesA, g_Wl + bsrc + kk);
            CP_COMMIT();
            CP_WAIT(1);
        } else {
            CP_WAIT(0);
        }
        __syncthreads();

        uint32_t aAh = smem_u32(sA[cur][0]), aAl = smem_u32(sA[cur][1]);
        uint32_t aBh = smem_u32(sB[cur][0]), aBl = smem_u32(sB[cur][1]);
#pragma unroll
        for (int ks = 0; ks < 32; ks += 16) {
            uint32_t ah[2][4], al[2][4], bh[2][2], bl[2][2];
#pragma unroll
            for (int i = 0; i < 2; i++) {
                uint32_t ad = a_off + 2u * (i * 16 * STRIDE + ks);
                ldmatrix_x4(ah[i][0], ah[i][1], ah[i][2], ah[i][3], aAh + ad);
                ldmatrix_x4(al[i][0], al[i][1], al[i][2], al[i][3], aAl + ad);
            }
            {
                uint32_t bd = b_off + 2u * ks;
                ldmatrix_x4(bh[0][0], bh[0][1], bh[1][0], bh[1][1], aBh + bd);
                ldmatrix_x4(bl[0][0], bl[0][1], bl[1][0], bl[1][1], aBl + bd);
            }
#pragma unroll
            for (int i = 0; i < 2; i++)
#pragma unroll
                for (int j = 0; j < 2; j++) {
                    mma_bf16(acc[i][j], ah[i], bh[j]);
                    mma_bf16(acc[i][j], al[i], bh[j]);
                    mma_bf16(acc[i][j], ah[i], bl[j]);
                }
        }
        __syncthreads();
    }

    // ---- store h + fused f_src/f_dst partials ----
    float as01[2][2], ad01[2][2];
#pragma unroll
    for (int j = 0; j < 2; j++) {
        int c = head * 64 + wn + j * 8 + (lane & 3) * 2;
        as01[j][0] = a_src[c];
        as01[j][1] = a_src[c + 1];
        ad01[j][0] = a_dst[c];
        ad01[j][1] = a_dst[c + 1];
    }
#pragma unroll
    for (int i = 0; i < 2; i++) {
        int r0 = n0 + wm + i * 16 + (lane >> 2);
#pragma unroll
        for (int j = 0; j < 2; j++) {
            int c = c0 + wn + j * 8 + (lane & 3) * 2;
            *(float2*)(g_h + (size_t)r0 * COLS + c) = make_float2(acc[i][j][0], acc[i][j][1]);
            *(float2*)(g_h + (size_t)(r0 + 8) * COLS + c) = make_float2(acc[i][j][2], acc[i][j][3]);
        }
        float fs0 = 0.f, fs1 = 0.f, fd0 = 0.f, fd1 = 0.f;
#pragma unroll
        for (int j = 0; j < 2; j++) {
            fs0 += acc[i][j][0] * as01[j][0] + acc[i][j][1] * as01[j][1];
            fs1 += acc[i][j][2] * as01[j][0] + acc[i][j][3] * as01[j][1];
            fd0 += acc[i][j][0] * ad01[j][0] + acc[i][j][1] * ad01[j][1];
            fd1 += acc[i][j][2] * ad01[j][0] + acc[i][j][3] * ad01[j][1];
        }
#pragma unroll
        for (int off = 1; off <= 2; off <<= 1) {
            fs0 += __shfl_xor_sync(0xffffffffu, fs0, off);
            fs1 += __shfl_xor_sync(0xffffffffu, fs1, off);
            fd0 += __shfl_xor_sync(0xffffffffu, fd0, off);
            fd1 += __shfl_xor_sync(0xffffffffu, fd1, off);
        }
        if ((lane & 3) == 0) {
            int r = wm + i * 16 + (lane >> 2);
            int cw = wid >> 1;
            s_fs[cw][r] = fs0;
            s_fs[cw][r + 8] = fs1;
            s_fd[cw][r] = fd0;
            s_fd[cw][r + 8] = fd1;
        }
    }
    __syncthreads();
    if (t < 64) {
        float fs = s_fs[0][t] + s_fs[1][t] + s_fs[2][t] + s_fs[3][t];
        float fd = s_fd[0][t] + s_fd[1][t] + s_fd[2][t] + s_fd[3][t];
        g_fs8[(n0 + t) * HEADS + head] = fs;
        g_fd8[(n0 + t) * HEADS + head] = fd;
    }
}

// ---------------------------------------------------------------------------
// Kernel D: fused masked softmax + all-heads aggregation (float4 streams).
// ---------------------------------------------------------------------------
__global__ __launch_bounds__(256) void gat_attn(const float* __restrict__ adj,
                                                float* __restrict__ out) {
    int i = blockIdx.x;
    int t = threadIdx.x;
    int lane = t & 31, wid = t >> 5;
    int head8 = t & 7;

    __shared__ int   s_idx[EMAX];
    __shared__ float s_w[EMAX][8];
    __shared__ float s_agg[8][512];
    __shared__ float s_red[8][8];
    __shared__ float s_m[8], s_inv[8], s_fs[8];
    __shared__ int   s_wsum[8];
    __shared__ int   s_total;

    // ---- Phase A: scan adjacency row, deterministic compaction ----
    const float4* arow4 = (const float4*)(adj + (size_t)i * NN);
    int lidx[12];
    int cnt = 0;
#pragma unroll
    for (int it = 0; it < 3; it++) {
        int q = t + it * 256;
        float4 v = arow4[q];
        int j = q * 4;
        if (v.x > 0.f) lidx[cnt++] = j;
        if (v.y > 0.f) lidx[cnt++] = j + 1;
        if (v.z > 0.f) lidx[cnt++] = j + 2;
        if (v.w > 0.f) lidx[cnt++] = j + 3;
    }
    int incl = cnt;
#pragma unroll
    for (int off = 1; off < 32; off <<= 1) {
        int nv = __shfl_up_sync(0xffffffffu, incl, off);
        if (lane >= off) incl += nv;
    }
    if (lane == 31) s_wsum[wid] = incl;
    if (t < 8) s_fs[t] = g_fs8[i * HEADS + t];
    __syncthreads();
    if (t == 0) {
        int s = 0;
#pragma unroll
        for (int w = 0; w < 8; w++) { int v = s_wsum[w]; s_wsum[w] = s; s += v; }
        s_total = s;
    }
    __syncthreads();
    int base = s_wsum[wid] + incl - cnt;
    for (int k = 0; k < cnt; k++)
        if (base + k < EMAX) s_idx[base + k] = lidx[k];
    __syncthreads();
    int E = min(s_total, EMAX);

    // ---- Phase B: logits + per-head softmax weights ----
    float fsv = s_fs[head8];
    float m = -1e30f;
    for (int k = (t >> 3); k < E; k += 32) {
        float e = fsv + g_fd8[s_idx[k] * HEADS + head8];
        e = (e > 0.f) ? e : NEG_SLOPE * e;
        s_w[k][head8] = e;
        m = fmaxf(m, e);
    }
    m = fmaxf(m, __shfl_xor_sync(0xffffffffu, m, 8));
    m = fmaxf(m, __shfl_xor_sync(0xffffffffu, m, 16));
    if (lane < 8) s_red[wid][lane] = m;
    __syncthreads();
    if (t < 8) {
        float mm = s_red[0][t];
#pragma unroll
        for (int w = 1; w < 8; w++) mm = fmaxf(mm, s_red[w][t]);
        s_m[t] = mm;
    }
    __syncthreads();

    float mh = s_m[head8];
    float sum = 0.f;
    for (int k = (t >> 3); k < E; k += 32) {
        float w = __expf(s_w[k][head8] - mh);
        s_w[k][head8] = w;
        sum += w;
    }
    sum += __shfl_xor_sync(0xffffffffu, sum, 8);
    sum += __shfl_xor_sync(0xffffffffu, sum, 16);
    if (lane < 8) s_red[wid][lane] = sum;
    __syncthreads();
    if (t < 8) {
        float ss = s_red[0][t];
#pragma unroll
        for (int w = 1; w < 8; w++) ss += s_red[w][t];
        s_inv[t] = 1.f / ss;
    }
    __syncthreads();

    // ---- Phase C: aggregation, warp per edge-stride, float4 streams ----
    float4 acc4[4] = {};
    bool hi_half = (lane >= 16);
    for (int k = wid; k < E; k += 8) {
        int j = s_idx[k];
        float4 wa = *(const float4*)&s_w[k][0];
        float4 wb = *(const float4*)&s_w[k][4];
        float w0 = hi_half ? wa.y : wa.x;
        float w1 = hi_half ? wa.w : wa.z;
        float w2 = hi_half ? wb.y : wb.x;
        float w3 = hi_half ? wb.w : wb.z;
        const float4* hr4 = (const float4*)(g_h + (size_t)j * COLS);
        float4 v0 = hr4[lane];
        float4 v1 = hr4[lane + 32];
        float4 v2 = hr4[lane + 64];
        float4 v3 = hr4[lane + 96];
        acc4[0].x += w0 * v0.x; acc4[0].y += w0 * v0.y; acc4[0].z += w0 * v0.z; acc4[0].w += w0 * v0.w;
        acc4[1].x += w1 * v1.x; acc4[1].y += w1 * v1.y; acc4[1].z += w1 * v1.z; acc4[1].w += w1 * v1.w;
        acc4[2].x += w2 * v2.x; acc4[2].y += w2 * v2.y; acc4[2].z += w2 * v2.z; acc4[2].w += w2 * v2.w;
        acc4[3].x += w3 * v3.x; acc4[3].y += w3 * v3.y; acc4[3].z += w3 * v3.z; acc4[3].w += w3 * v3.w;
    }
    float4* sa4 = (float4*)s_agg[wid];
#pragma unroll
    for (int q = 0; q < 4; q++) sa4[lane + q * 32] = acc4[q];
    __syncthreads();

    // ---- final cross-warp reduce + normalize (float4 cols) ----
    if (t < 128) {
        float4 s = ((const float4*)s_agg[0])[t];
#pragma unroll
        for (int w = 1; w < 8; w++) {
            float4 v = ((const float4*)s_agg[w])[t];
            s.x += v.x; s.y += v.y; s.z += v.z; s.w += v.w;
        }
        float inv = s_inv[t >> 4];
        ((float4*)(out + (size_t)i * COLS))[t] =
            make_float4(s.x * inv, s.y * inv, s.z * inv, s.w * inv);
    }
}

// ---------------------------------------------------------------------------
extern "C" void kernel_launch(void* const* d_in, const int* in_sizes, int n_in,
                              void* d_out, int out_size) {
    const float* x     = (const float*)d_in[0];
    const float* adj   = (const float*)d_in[1];
    const float* W     = (const float*)d_in[2];
    const float* a_src = (const float*)d_in[3];
    const float* a_dst = (const float*)d_in[4];
    float* out = (float*)d_out;

    x_split<<<NN * IN_DIM / 1024, 256>>>(x);
    w_split<<<dim3(HEADS, IN_DIM / 64), 256>>>(W);
    gat_gemm<<<dim3(NN / 64, COLS / 64), 256>>>(a_src, a_dst);
    gat_attn<<<NN, 256>>>(adj, out);
}